// round 4
// baseline (speedup 1.0000x reference)
#include <cuda_runtime.h>
#include <math.h>

#define BATCH 4
#define HW 4096
#define CH 512
#define NGROUP 32
#define CPG 16
#define EPSV 1e-6f

// ---- scratch (allocation-free rule: __device__ globals) ----
__device__ float g_stats[BATCH * NGROUP * 2];
__device__ float g_x[BATCH * HW * CH];
__device__ float g_q[BATCH * HW * CH];
__device__ float g_k[BATCH * HW * CH];
__device__ float g_v[BATCH * HW * CH];
__device__ float g_ao[BATCH * HW * CH];
__device__ float g_s[(size_t)BATCH * HW * HW];   // 256 MB scores

// ---------------- GroupNorm stats: one block per (b, g) ----------------
__global__ void gn_stats_kernel(const float* __restrict__ x) {
    int bg = blockIdx.x;
    int b = bg >> 5, g = bg & 31;
    const float* base = x + (size_t)b * HW * CH + g * CPG;
    float s = 0.f, ss = 0.f;
    for (int p = threadIdx.x; p < HW; p += blockDim.x) {
        const float4* r = (const float4*)(base + (size_t)p * CH);
#pragma unroll
        for (int i = 0; i < 4; i++) {
            float4 v = r[i];
            s  += v.x + v.y + v.z + v.w;
            ss += v.x * v.x + v.y * v.y + v.z * v.z + v.w * v.w;
        }
    }
    __shared__ float sh[256], sh2[256];
    int t = threadIdx.x;
    sh[t] = s; sh2[t] = ss;
    __syncthreads();
    for (int o = 128; o > 0; o >>= 1) {
        if (t < o) { sh[t] += sh[t + o]; sh2[t] += sh2[t + o]; }
        __syncthreads();
    }
    if (t == 0) {
        float inv = 1.f / (float)(HW * CPG);
        float mean = sh[0] * inv;
        float var = sh2[0] * inv - mean * mean;
        g_stats[bg * 2]     = mean;
        g_stats[bg * 2 + 1] = rsqrtf(var + EPSV);
    }
}

// ---------------- GroupNorm apply ----------------
__global__ void gn_apply_kernel(const float* __restrict__ x,
                                const float* __restrict__ gamma,
                                const float* __restrict__ beta) {
    size_t i = ((size_t)blockIdx.x * blockDim.x + threadIdx.x) * 4;
    int c = (int)(i % CH);
    int b = (int)(i / ((size_t)HW * CH));
    int bg = b * NGROUP + (c >> 4);
    float mean = g_stats[bg * 2], rstd = g_stats[bg * 2 + 1];
    float4 v  = *(const float4*)(x + i);
    float4 ga = *(const float4*)(gamma + c);
    float4 be = *(const float4*)(beta + c);
    float4 o;
    o.x = (v.x - mean) * rstd * ga.x + be.x;
    o.y = (v.y - mean) * rstd * ga.y + be.y;
    o.z = (v.z - mean) * rstd * ga.z + be.z;
    o.w = (v.w - mean) * rstd * ga.w + be.w;
    *(float4*)(g_x + i) = o;
}

// ---------------- 128x128x8 fp32 SGEMM, double-buffered ----------------
// C = (A @ B (+bias)) * alpha (+res).  TRANSB: B is [N,K] row-major (B^T used).
template <bool TRANSB>
__global__ void __launch_bounds__(256) sgemm_kernel(
    const float* __restrict__ A, const float* __restrict__ Bm, float* __restrict__ Cm,
    int M, int N, int K, long long sA, long long sB, long long sC,
    const float* __restrict__ bias, const float* __restrict__ res, float alpha) {
    __shared__ float As[2][8][128];
    __shared__ float Bs[2][8][128];
    int tid = threadIdx.x;
    const float* Ab = A + (size_t)blockIdx.z * sA + (size_t)(blockIdx.y * 128) * K;
    const float* Bb;
    if (TRANSB) Bb = Bm + (size_t)blockIdx.z * sB + (size_t)(blockIdx.x * 128) * K;
    else        Bb = Bm + (size_t)blockIdx.z * sB + (blockIdx.x * 128);

    int lrow = tid >> 1;          // 0..127
    int lcol = (tid & 1) * 4;     // 0 / 4
    int brow = tid >> 5;          // 0..7
    int bcol = (tid & 31) * 4;    // 0..124
    int tx = tid & 15, ty = tid >> 4;

    float acc[8][8];
#pragma unroll
    for (int i = 0; i < 8; i++)
#pragma unroll
        for (int j = 0; j < 8; j++) acc[i][j] = 0.f;

    // ---- preload tile 0 into buffer 0 ----
    {
        float4 a = *(const float4*)(Ab + (size_t)lrow * K + lcol);
        As[0][lcol + 0][lrow] = a.x; As[0][lcol + 1][lrow] = a.y;
        As[0][lcol + 2][lrow] = a.z; As[0][lcol + 3][lrow] = a.w;
        if (TRANSB) {
            float4 bv = *(const float4*)(Bb + (size_t)lrow * K + lcol);
            Bs[0][lcol + 0][lrow] = bv.x; Bs[0][lcol + 1][lrow] = bv.y;
            Bs[0][lcol + 2][lrow] = bv.z; Bs[0][lcol + 3][lrow] = bv.w;
        } else {
            float4 bv = *(const float4*)(Bb + (size_t)brow * N + bcol);
            *(float4*)&Bs[0][brow][bcol] = bv;
        }
    }
    __syncthreads();

    int buf = 0;
    for (int k0 = 0; k0 < K; k0 += 8) {
        float4 a_n, b_n;
        bool has_next = (k0 + 8 < K);
        if (has_next) {
            a_n = *(const float4*)(Ab + (size_t)lrow * K + (k0 + 8) + lcol);
            if (TRANSB)
                b_n = *(const float4*)(Bb + (size_t)lrow * K + (k0 + 8) + lcol);
            else
                b_n = *(const float4*)(Bb + (size_t)(k0 + 8 + brow) * N + bcol);
        }
#pragma unroll
        for (int kk = 0; kk < 8; kk++) {
            float ra[8], rb[8];
            *(float4*)&ra[0] = *(const float4*)&As[buf][kk][ty * 8];
            *(float4*)&ra[4] = *(const float4*)&As[buf][kk][ty * 8 + 4];
            *(float4*)&rb[0] = *(const float4*)&Bs[buf][kk][tx * 8];
            *(float4*)&rb[4] = *(const float4*)&Bs[buf][kk][tx * 8 + 4];
#pragma unroll
            for (int i = 0; i < 8; i++)
#pragma unroll
                for (int j = 0; j < 8; j++)
                    acc[i][j] += ra[i] * rb[j];
        }
        if (has_next) {
            int nb = buf ^ 1;
            As[nb][lcol + 0][lrow] = a_n.x; As[nb][lcol + 1][lrow] = a_n.y;
            As[nb][lcol + 2][lrow] = a_n.z; As[nb][lcol + 3][lrow] = a_n.w;
            if (TRANSB) {
                Bs[nb][lcol + 0][lrow] = b_n.x; Bs[nb][lcol + 1][lrow] = b_n.y;
                Bs[nb][lcol + 2][lrow] = b_n.z; Bs[nb][lcol + 3][lrow] = b_n.w;
            } else {
                *(float4*)&Bs[nb][brow][bcol] = b_n;
            }
        }
        __syncthreads();
        buf ^= 1;
    }

    int row0 = blockIdx.y * 128 + ty * 8;
    int col0 = blockIdx.x * 128 + tx * 8;
    float* Cb = Cm + (size_t)blockIdx.z * sC;
    const float* resb = res ? (res + (size_t)blockIdx.z * sC) : (const float*)0;
#pragma unroll
    for (int i = 0; i < 8; i++) {
#pragma unroll
        for (int j = 0; j < 8; j++) {
            float v = acc[i][j];
            if (bias) v += bias[col0 + j];
            v *= alpha;
            if (resb) v += resb[(size_t)(row0 + i) * N + col0 + j];
            Cb[(size_t)(row0 + i) * N + col0 + j] = v;
        }
    }
}

// ---------------- row softmax over 4096 ----------------
__global__ void softmax_kernel(float* __restrict__ S) {
    size_t row = blockIdx.x;
    float* p = S + row * HW;
    int t = threadIdx.x;
    float v[16];
    float m = -1e30f;
#pragma unroll
    for (int i = 0; i < 16; i++) { v[i] = p[i * 256 + t]; m = fmaxf(m, v[i]); }
    __shared__ float sh[256];
    sh[t] = m; __syncthreads();
    for (int o = 128; o > 0; o >>= 1) { if (t < o) sh[t] = fmaxf(sh[t], sh[t + o]); __syncthreads(); }
    m = sh[0];
    __syncthreads();
    float s = 0.f;
#pragma unroll
    for (int i = 0; i < 16; i++) { v[i] = __expf(v[i] - m); s += v[i]; }
    sh[t] = s; __syncthreads();
    for (int o = 128; o > 0; o >>= 1) { if (t < o) sh[t] += sh[t + o]; __syncthreads(); }
    float inv = 1.f / sh[0];
#pragma unroll
    for (int i = 0; i < 16; i++) p[i * 256 + t] = v[i] * inv;
}

extern "C" void kernel_launch(void* const* d_in, const int* in_sizes, int n_in,
                              void* d_out, int out_size) {
    const float* x     = (const float*)d_in[0];
    const float* gamma = (const float*)d_in[1];
    const float* beta  = (const float*)d_in[2];
    const float* wq    = (const float*)d_in[3];
    const float* bq    = (const float*)d_in[4];
    const float* wk    = (const float*)d_in[5];
    const float* bk    = (const float*)d_in[6];
    const float* wv    = (const float*)d_in[7];
    const float* bv    = (const float*)d_in[8];
    const float* wo    = (const float*)d_in[9];
    const float* bo    = (const float*)d_in[10];
    float* out = (float*)d_out;

    float *px, *pq, *pk, *pv, *pao, *ps;
    cudaGetSymbolAddress((void**)&px,  g_x);
    cudaGetSymbolAddress((void**)&pq,  g_q);
    cudaGetSymbolAddress((void**)&pk,  g_k);
    cudaGetSymbolAddress((void**)&pv,  g_v);
    cudaGetSymbolAddress((void**)&pao, g_ao);
    cudaGetSymbolAddress((void**)&ps,  g_s);

    gn_stats_kernel<<<BATCH * NGROUP, 256>>>(x);
    gn_apply_kernel<<<(BATCH * HW * CH / 4) / 256, 256>>>(x, gamma, beta);

    const float scale = 0.0441941738241592f;  // 1/sqrt(512)
    dim3 gp(CH / 128, (BATCH * HW) / 128, 1);          // (4,128)
    sgemm_kernel<false><<<gp, 256>>>(px, wq, pq, BATCH * HW, CH, CH, 0, 0, 0, bq, 0, scale);
    sgemm_kernel<false><<<gp, 256>>>(px, wk, pk, BATCH * HW, CH, CH, 0, 0, 0, bk, 0, 1.f);
    sgemm_kernel<false><<<gp, 256>>>(px, wv, pv, BATCH * HW, CH, CH, 0, 0, 0, bv, 0, 1.f);

    dim3 gs(HW / 128, HW / 128, BATCH);                // (32,32,4)
    sgemm_kernel<true><<<gs, 256>>>(pq, pk, ps, HW, HW, CH,
                                    (long long)HW * CH, (long long)HW * CH,
                                    (long long)HW * HW, 0, 0, 1.f);

    softmax_kernel<<<BATCH * HW, 256>>>(ps);

    dim3 gav(CH / 128, HW / 128, BATCH);               // (4,32,4)
    sgemm_kernel<false><<<gav, 256>>>(ps, pv, pao, HW, CH, HW,
                                      (long long)HW * HW, (long long)HW * CH,
                                      (long long)HW * CH, 0, 0, 1.f);

    sgemm_kernel<false><<<gp, 256>>>(pao, wo, out, BATCH * HW, CH, CH, 0, 0, 0, bo, x, 1.f);
}

// round 8
// speedup vs baseline: 4.5798x; 4.5798x over previous
#include <cuda_runtime.h>
#include <cuda_bf16.h>
#include <math.h>
#include <stdint.h>

#define BATCH 4
#define HW 4096
#define CH 512
#define NGROUP 32
#define CPG 16
#define EPSV 1e-6f

typedef __nv_bfloat16 bf16;

// ---------------- scratch (__device__ globals; allocation-free rule) ----------------
__device__ float g_stats[BATCH * NGROUP * 2];
__device__ __align__(256) bf16 g_xb [BATCH * HW * CH];
__device__ __align__(256) bf16 g_qb [BATCH * HW * CH];
__device__ __align__(256) bf16 g_kb [BATCH * HW * CH];
__device__ __align__(256) bf16 g_vb [BATCH * HW * CH];
__device__ __align__(256) bf16 g_vt [BATCH * HW * CH];          // V^T [B][C][N]
__device__ __align__(256) bf16 g_aob[BATCH * HW * CH];
__device__ __align__(256) float g_s [(size_t)BATCH * HW * HW];  // fp32 scores (256 MB)
__device__ __align__(256) bf16 g_pb [(size_t)BATCH * HW * HW];  // bf16 probs (128 MB)
__device__ __align__(256) bf16 g_wqT[CH * CH];
__device__ __align__(256) bf16 g_wkT[CH * CH];
__device__ __align__(256) bf16 g_wvT[CH * CH];
__device__ __align__(256) bf16 g_woT[CH * CH];

// ================= warp-MMA helpers (sm_80+ path; valid on plain sm_103 target) =======
__device__ __forceinline__ uint32_t smem_u32(const void* p) {
    uint32_t a;
    asm("{ .reg .u64 t; cvta.to.shared.u64 t, %1; cvt.u32.u64 %0, t; }" : "=r"(a) : "l"(p));
    return a;
}
__device__ __forceinline__ void cp16(uint32_t saddr, const void* g) {
    asm volatile("cp.async.cg.shared.global [%0], [%1], 16;" :: "r"(saddr), "l"(g));
}
#define CP_COMMIT() asm volatile("cp.async.commit_group;" ::: "memory")
#define CP_WAIT0()  asm volatile("cp.async.wait_group 0;" ::: "memory")

__device__ __forceinline__ void ldsm4(uint32_t (&r)[4], uint32_t addr) {
    asm volatile("ldmatrix.sync.aligned.m8n8.x4.shared.b16 {%0,%1,%2,%3}, [%4];"
                 : "=r"(r[0]), "=r"(r[1]), "=r"(r[2]), "=r"(r[3]) : "r"(addr));
}
__device__ __forceinline__ void mma16816(float* d, const uint32_t* a, const uint32_t* b) {
    asm volatile(
        "mma.sync.aligned.m16n8k16.row.col.f32.bf16.bf16.f32 "
        "{%0,%1,%2,%3}, {%4,%5,%6,%7}, {%8,%9}, {%0,%1,%2,%3};"
        : "+f"(d[0]), "+f"(d[1]), "+f"(d[2]), "+f"(d[3])
        : "r"(a[0]), "r"(a[1]), "r"(a[2]), "r"(a[3]), "r"(b[0]), "r"(b[1]));
}

// smem tile: 128 rows x 32 bf16 cols = 128 x 64B; 4 chunks of 16B per row,
// chunk swizzle: c ^= (row>>1)&3  (conflict-free for STS and ldmatrix phases)
__device__ __forceinline__ uint32_t tile_off(int r, int c) {
    return (uint32_t)(r * 64 + ((c ^ ((r >> 1) & 3)) << 4));
}

// ================= 128x128x32 double-buffered bf16 warp-MMA GEMM =================
// D[128*by + r][128*bx + c] = sum_k A[r,k] * B[c,k]   (A,B K-major bf16)
// epilogue: v = acc (+bias[col]); v *= alpha; (+res); store float or bf16
template <typename OT>
__global__ void __launch_bounds__(256, 1) wmma_gemm(
    const bf16* __restrict__ A, const bf16* __restrict__ B, OT* __restrict__ C,
    int K, int ldC, long long sA, long long sB, long long sC,
    const float* __restrict__ bias, const float* __restrict__ res, float alpha) {
    __shared__ __align__(128) unsigned char sm[2][2][8192];   // [buf][A/B][tile]
    const int tid = threadIdx.x, wid = tid >> 5, lane = tid & 31;
    const int wm = wid & 3, wn = wid >> 2;                    // warps 4x2
    const bf16* Ab = A + (size_t)blockIdx.z * sA + (size_t)(blockIdx.y * 128) * K;
    const bf16* Bb = B + (size_t)blockIdx.z * sB + (size_t)(blockIdx.x * 128) * K;
    const uint32_t s0 = smem_u32(sm);

    // per-thread load coords (2 x 16B per tile per matrix)
    const int lr0 = tid >> 2, lc0 = tid & 3;                  // linear 0..255
    const int lr1 = (tid + 256) >> 2, lc1 = tid & 3;          // wraps chunk same
    const uint32_t soA0 = tile_off(lr0, lc0), soA1 = tile_off(lr1, lc1);

    float acc[2][8][4];
#pragma unroll
    for (int f = 0; f < 2; f++)
#pragma unroll
        for (int j = 0; j < 8; j++)
#pragma unroll
            for (int e = 0; e < 4; e++) acc[f][j][e] = 0.f;

    // ldmatrix per-lane row/chunk partials
    const int mid = lane >> 3;                                // 0..3
    const int lrow = ((mid & 1) << 3) + (lane & 7);           // row within 16
    const int lchk = mid >> 1;                                // 0/1 within k16

    // ---- preload tile 0 ----
    {
        cp16(s0 + soA0, Ab + (size_t)lr0 * K + (lc0 << 3));
        cp16(s0 + soA1, Ab + (size_t)lr1 * K + (lc1 << 3));
        cp16(s0 + 8192 + soA0, Bb + (size_t)lr0 * K + (lc0 << 3));
        cp16(s0 + 8192 + soA1, Bb + (size_t)lr1 * K + (lc1 << 3));
        CP_COMMIT();
    }

    const int nt = K >> 5;
    int buf = 0;
    for (int t = 0; t < nt; t++) {
        CP_WAIT0();
        __syncthreads();
        if (t + 1 < nt) {
            uint32_t d = s0 + (buf ^ 1) * 16384;
            const bf16* An = Ab + (t + 1) * 32;
            const bf16* Bn = Bb + (t + 1) * 32;
            cp16(d + soA0, An + (size_t)lr0 * K + (lc0 << 3));
            cp16(d + soA1, An + (size_t)lr1 * K + (lc1 << 3));
            cp16(d + 8192 + soA0, Bn + (size_t)lr0 * K + (lc0 << 3));
            cp16(d + 8192 + soA1, Bn + (size_t)lr1 * K + (lc1 << 3));
            CP_COMMIT();
        }
        const uint32_t aB = s0 + buf * 16384;
        const uint32_t bB = aB + 8192;
#pragma unroll
        for (int s = 0; s < 2; s++) {                         // two k16 steps
            uint32_t a[2][4], b[8][2];
#pragma unroll
            for (int f = 0; f < 2; f++) {
                int r = wm * 32 + f * 16 + lrow;
                ldsm4(a[f], aB + tile_off(r, s * 2 + lchk));
            }
#pragma unroll
            for (int gq = 0; gq < 4; gq++) {
                int r = wn * 64 + gq * 16 + lrow;
                uint32_t rr[4];
                ldsm4(rr, bB + tile_off(r, s * 2 + lchk));
                b[gq * 2][0] = rr[0]; b[gq * 2][1] = rr[2];
                b[gq * 2 + 1][0] = rr[1]; b[gq * 2 + 1][1] = rr[3];
            }
#pragma unroll
            for (int f = 0; f < 2; f++)
#pragma unroll
                for (int j = 0; j < 8; j++) mma16816(acc[f][j], a[f], b[j]);
        }
        __syncthreads();
        buf ^= 1;
    }

    // ---- epilogue ----
    const int g = lane >> 2, t2 = (lane & 3) << 1;
    const int row0 = blockIdx.y * 128 + wm * 32;
    const int col0 = blockIdx.x * 128 + wn * 64;
    OT* Cb = C + (size_t)blockIdx.z * sC;
    const float* resb = res ? (res + (size_t)blockIdx.z * sC) : (const float*)0;
#pragma unroll
    for (int f = 0; f < 2; f++) {
#pragma unroll
        for (int j = 0; j < 8; j++) {
            int cc = col0 + j * 8 + t2;
            float b0 = 0.f, b1 = 0.f;
            if (bias) { b0 = bias[cc]; b1 = bias[cc + 1]; }
#pragma unroll
            for (int h = 0; h < 2; h++) {                     // rows g / g+8
                int rr = row0 + f * 16 + g + h * 8;
                float v0 = (acc[f][j][h * 2 + 0] + b0) * alpha;
                float v1 = (acc[f][j][h * 2 + 1] + b1) * alpha;
                size_t o = (size_t)rr * ldC + cc;
                if (resb) { v0 += resb[o]; v1 += resb[o + 1]; }
                if (sizeof(OT) == 4) {
                    float2 w = make_float2(v0, v1);
                    *(float2*)((float*)Cb + o) = w;
                } else {
                    __nv_bfloat162 w;
                    w.x = __float2bfloat16(v0); w.y = __float2bfloat16(v1);
                    *(__nv_bfloat162*)((bf16*)Cb + o) = w;
                }
            }
        }
    }
}

// ---------------- GroupNorm stats ----------------
__global__ void gn_stats_kernel(const float* __restrict__ x) {
    int bg = blockIdx.x;
    int b = bg >> 5, g = bg & 31;
    const float* base = x + (size_t)b * HW * CH + g * CPG;
    float s = 0.f, ss = 0.f;
    for (int p = threadIdx.x; p < HW; p += blockDim.x) {
        const float4* r = (const float4*)(base + (size_t)p * CH);
#pragma unroll
        for (int i = 0; i < 4; i++) {
            float4 v = r[i];
            s  += v.x + v.y + v.z + v.w;
            ss += v.x * v.x + v.y * v.y + v.z * v.z + v.w * v.w;
        }
    }
    __shared__ float sh[256], sh2[256];
    int t = threadIdx.x;
    sh[t] = s; sh2[t] = ss;
    __syncthreads();
    for (int o = 128; o > 0; o >>= 1) {
        if (t < o) { sh[t] += sh[t + o]; sh2[t] += sh2[t + o]; }
        __syncthreads();
    }
    if (t == 0) {
        float inv = 1.f / (float)(HW * CPG);
        float mean = sh[0] * inv;
        float var = sh2[0] * inv - mean * mean;
        g_stats[bg * 2]     = mean;
        g_stats[bg * 2 + 1] = rsqrtf(var + EPSV);
    }
}

// ---------------- GroupNorm apply -> bf16 ----------------
__global__ void gn_apply_kernel(const float* __restrict__ x,
                                const float* __restrict__ gamma,
                                const float* __restrict__ beta) {
    size_t i = ((size_t)blockIdx.x * blockDim.x + threadIdx.x) * 4;
    int c = (int)(i % CH);
    int b = (int)(i / ((size_t)HW * CH));
    int bg = b * NGROUP + (c >> 4);
    float mean = g_stats[bg * 2], rstd = g_stats[bg * 2 + 1];
    float4 v  = *(const float4*)(x + i);
    float4 ga = *(const float4*)(gamma + c);
    float4 be = *(const float4*)(beta + c);
    __nv_bfloat162 o01, o23;
    o01.x = __float2bfloat16((v.x - mean) * rstd * ga.x + be.x);
    o01.y = __float2bfloat16((v.y - mean) * rstd * ga.y + be.y);
    o23.x = __float2bfloat16((v.z - mean) * rstd * ga.z + be.z);
    o23.y = __float2bfloat16((v.w - mean) * rstd * ga.w + be.w);
    *(__nv_bfloat162*)(g_xb + i)     = o01;
    *(__nv_bfloat162*)(g_xb + i + 2) = o23;
}

// ---------------- weight transpose fp32 [K,N] -> bf16 [N,K] ----------------
__global__ void transpose_w_kernel(const float* __restrict__ w, bf16* __restrict__ wT) {
    __shared__ float t[32][33];
    int c0 = blockIdx.x * 32, d0 = blockIdx.y * 32;
    int tx = threadIdx.x, ty = threadIdx.y;
#pragma unroll
    for (int r = 0; r < 4; r++) {
        int row = ty + r * 8;
        t[row][tx] = w[(size_t)(c0 + row) * CH + d0 + tx];
    }
    __syncthreads();
#pragma unroll
    for (int r = 0; r < 4; r++) {
        int row = ty + r * 8;
        wT[(size_t)(d0 + row) * CH + c0 + tx] = __float2bfloat16(t[tx][row]);
    }
}

// ---------------- V transpose bf16 [B][N][C] -> [B][C][N] ----------------
__global__ void transpose_v_kernel() {
    __shared__ bf16 t[32][33];
    int c0 = blockIdx.x * 32, n0 = blockIdx.y * 32, b = blockIdx.z;
    int tx = threadIdx.x, ty = threadIdx.y;
#pragma unroll
    for (int r = 0; r < 4; r++) {
        int row = ty + r * 8;
        t[row][tx] = g_vb[((size_t)b * HW + n0 + row) * CH + c0 + tx];
    }
    __syncthreads();
#pragma unroll
    for (int r = 0; r < 4; r++) {
        int row = ty + r * 8;
        g_vt[((size_t)b * CH + c0 + row) * HW + n0 + tx] = t[tx][row];
    }
}

// ---------------- row softmax (fp32 in -> bf16 out) ----------------
__global__ void softmax_kernel(const float* __restrict__ S, bf16* __restrict__ P) {
    size_t row = blockIdx.x;
    const float* p = S + row * HW;
    bf16* q = P + row * HW;
    int t = threadIdx.x;
    float v[16];
    float m = -1e30f;
#pragma unroll
    for (int i = 0; i < 16; i++) { v[i] = p[i * 256 + t]; m = fmaxf(m, v[i]); }
    __shared__ float sh[256];
    sh[t] = m; __syncthreads();
    for (int o = 128; o > 0; o >>= 1) { if (t < o) sh[t] = fmaxf(sh[t], sh[t + o]); __syncthreads(); }
    m = sh[0];
    __syncthreads();
    float s = 0.f;
#pragma unroll
    for (int i = 0; i < 16; i++) { v[i] = __expf(v[i] - m); s += v[i]; }
    sh[t] = s; __syncthreads();
    for (int o = 128; o > 0; o >>= 1) { if (t < o) sh[t] += sh[t + o]; __syncthreads(); }
    float inv = 1.f / sh[0];
#pragma unroll
    for (int i = 0; i < 16; i++) q[i * 256 + t] = __float2bfloat16(v[i] * inv);
}

extern "C" void kernel_launch(void* const* d_in, const int* in_sizes, int n_in,
                              void* d_out, int out_size) {
    const float* x     = (const float*)d_in[0];
    const float* gamma = (const float*)d_in[1];
    const float* beta  = (const float*)d_in[2];
    const float* wq    = (const float*)d_in[3];
    const float* bq    = (const float*)d_in[4];
    const float* wk    = (const float*)d_in[5];
    const float* bk    = (const float*)d_in[6];
    const float* wv    = (const float*)d_in[7];
    const float* bv    = (const float*)d_in[8];
    const float* wo    = (const float*)d_in[9];
    const float* bo    = (const float*)d_in[10];
    float* out = (float*)d_out;

    bf16 *pxb, *pqb, *pkb, *pvb, *pvt, *paob, *ppb;
    bf16 *pwqT, *pwkT, *pwvT, *pwoT;
    float *ps;
    cudaGetSymbolAddress((void**)&pxb,  g_xb);
    cudaGetSymbolAddress((void**)&pqb,  g_qb);
    cudaGetSymbolAddress((void**)&pkb,  g_kb);
    cudaGetSymbolAddress((void**)&pvb,  g_vb);
    cudaGetSymbolAddress((void**)&pvt,  g_vt);
    cudaGetSymbolAddress((void**)&paob, g_aob);
    cudaGetSymbolAddress((void**)&ppb,  g_pb);
    cudaGetSymbolAddress((void**)&ps,   g_s);
    cudaGetSymbolAddress((void**)&pwqT, g_wqT);
    cudaGetSymbolAddress((void**)&pwkT, g_wkT);
    cudaGetSymbolAddress((void**)&pwvT, g_wvT);
    cudaGetSymbolAddress((void**)&pwoT, g_woT);

    // GroupNorm
    gn_stats_kernel<<<BATCH * NGROUP, 256>>>(x);
    gn_apply_kernel<<<(BATCH * HW * CH / 4) / 256, 256>>>(x, gamma, beta);

    // weight transposes (K-major bf16)
    dim3 bt(32, 8);
    dim3 gw(16, 16);
    transpose_w_kernel<<<gw, bt>>>(wq, pwqT);
    transpose_w_kernel<<<gw, bt>>>(wk, pwkT);
    transpose_w_kernel<<<gw, bt>>>(wv, pwvT);
    transpose_w_kernel<<<gw, bt>>>(wo, pwoT);

    const float scale = 0.0441941738241592f;  // 1/sqrt(512)

    // projections: [16384 x 512] x [512 x 512]
    dim3 gproj(CH / 128, (BATCH * HW) / 128, 1);  // (4, 128)
    wmma_gemm<bf16><<<gproj, 256>>>(pxb, pwqT, pqb, CH, CH, 0, 0, 0, bq, 0, scale);
    wmma_gemm<bf16><<<gproj, 256>>>(pxb, pwkT, pkb, CH, CH, 0, 0, 0, bk, 0, 1.f);
    wmma_gemm<bf16><<<gproj, 256>>>(pxb, pwvT, pvb, CH, CH, 0, 0, 0, bv, 0, 1.f);

    transpose_v_kernel<<<dim3(CH / 32, HW / 32, BATCH), bt>>>();

    // scores: per batch [4096 x 512] x [4096 x 512]^T -> fp32
    dim3 gsc(HW / 128, HW / 128, BATCH);  // (32, 32, 4)
    wmma_gemm<float><<<gsc, 256>>>(pqb, pkb, ps, CH, HW,
                                   (long long)HW * CH, (long long)HW * CH,
                                   (long long)HW * HW, 0, 0, 1.f);

    softmax_kernel<<<BATCH * HW, 256>>>(ps, ppb);

    // AV: per batch [4096 x 4096] x [512 x 4096]^T -> bf16
    dim3 gav(CH / 128, HW / 128, BATCH);  // (4, 32, 4)
    wmma_gemm<bf16><<<gav, 256>>>(ppb, pvt, paob, HW, CH,
                                  (long long)HW * HW, (long long)CH * HW,
                                  (long long)HW * CH, 0, 0, 1.f);

    // out projection + residual -> fp32 out
    wmma_gemm<float><<<gproj, 256>>>(paob, pwoT, out, CH, CH, 0, 0, 0, bo, x, 1.f);
}

// round 10
// speedup vs baseline: 5.6686x; 1.2377x over previous
#include <cuda_runtime.h>
#include <cuda_bf16.h>
#include <math.h>
#include <stdint.h>

#define BATCH 4
#define HW 4096
#define CH 512
#define NGROUP 32
#define CPG 16
#define EPSV 1e-6f

typedef __nv_bfloat16 bf16;

// ---------------- scratch (__device__ globals; allocation-free rule) ----------------
__device__ float g_stats[BATCH * NGROUP * 2];
__device__ __align__(256) bf16 g_xb [BATCH * HW * CH];
__device__ __align__(256) bf16 g_qb [BATCH * HW * CH];
__device__ __align__(256) bf16 g_kb [BATCH * HW * CH];
__device__ __align__(256) bf16 g_vt [BATCH * HW * CH];          // V^T [B][C][N]
__device__ __align__(256) bf16 g_aob[BATCH * HW * CH];
__device__ __align__(256) float g_s [(size_t)BATCH * HW * HW];  // fp32 scores (256 MB)
__device__ __align__(256) bf16 g_pb [(size_t)BATCH * HW * HW];  // bf16 probs (128 MB)
__device__ __align__(256) bf16 g_wqT[CH * CH];
__device__ __align__(256) bf16 g_wkT[CH * CH];
__device__ __align__(256) bf16 g_wvT[CH * CH];
__device__ __align__(256) bf16 g_woT[CH * CH];

// ================= warp-MMA helpers (sm_80+ path; valid on plain sm_103 target) =======
__device__ __forceinline__ uint32_t smem_u32(const void* p) {
    uint32_t a;
    asm("{ .reg .u64 t; cvta.to.shared.u64 t, %1; cvt.u32.u64 %0, t; }" : "=r"(a) : "l"(p));
    return a;
}
__device__ __forceinline__ void cp16(uint32_t saddr, const void* g) {
    asm volatile("cp.async.cg.shared.global [%0], [%1], 16;" :: "r"(saddr), "l"(g));
}
#define CP_COMMIT() asm volatile("cp.async.commit_group;" ::: "memory")
#define CP_WAIT0()  asm volatile("cp.async.wait_group 0;" ::: "memory")

__device__ __forceinline__ void ldsm4(uint32_t (&r)[4], uint32_t addr) {
    asm volatile("ldmatrix.sync.aligned.m8n8.x4.shared.b16 {%0,%1,%2,%3}, [%4];"
                 : "=r"(r[0]), "=r"(r[1]), "=r"(r[2]), "=r"(r[3]) : "r"(addr));
}
__device__ __forceinline__ void mma16816(float* d, const uint32_t* a, const uint32_t* b) {
    asm volatile(
        "mma.sync.aligned.m16n8k16.row.col.f32.bf16.bf16.f32 "
        "{%0,%1,%2,%3}, {%4,%5,%6,%7}, {%8,%9}, {%0,%1,%2,%3};"
        : "+f"(d[0]), "+f"(d[1]), "+f"(d[2]), "+f"(d[3])
        : "r"(a[0]), "r"(a[1]), "r"(a[2]), "r"(a[3]), "r"(b[0]), "r"(b[1]));
}

// smem tile: R rows x 32 bf16 = R x 64B; 4 chunks of 16B per row,
// chunk swizzle c ^= (row>>1)&3  (conflict-free for STS and ldmatrix; verified R7)
__device__ __forceinline__ uint32_t tile_off(int r, int c) {
    return (uint32_t)(r * 64 + ((c ^ ((r >> 1) & 3)) << 4));
}

// ================= 128xBN x32 double-buffered bf16 warp-MMA GEMM =================
// D[128*by + r][BN*bx + c] = sum_k A[r,k] * B[c,k]   (A,B K-major bf16)
// bias_mode: 0 none, 1 per-col, 2 per-row.  v = (acc + bias)*alpha (+res)
template <typename OT, int BN, int WARPS_M>
__global__ void __launch_bounds__(256, 1) wmma_gemm(
    const bf16* __restrict__ A, const bf16* __restrict__ B, OT* __restrict__ C,
    int K, int ldC, long long sA, long long sB, long long sC,
    const float* __restrict__ bias, int bias_mode,
    const float* __restrict__ res, float alpha) {
    constexpr int WARPS_N = 8 / WARPS_M;
    constexpr int WM = 128 / WARPS_M;          // warp rows
    constexpr int WN = BN / WARPS_N;           // warp cols (must be 64)
    constexpr int MF = WM / 16;                // m16 fragments per warp
    constexpr int ATILE = 128 * 64;            // bytes per A stage
    constexpr int BTILE = BN * 64;             // bytes per B stage
    static_assert(WN == 64, "warp N must be 64");
    __shared__ __align__(128) unsigned char sm[2][ATILE + BTILE];

    const int tid = threadIdx.x, wid = tid >> 5, lane = tid & 31;
    const int wm = wid % WARPS_M, wn = wid / WARPS_M;
    const bf16* Ab = A + (size_t)blockIdx.z * sA + (size_t)(blockIdx.y * 128) * K;
    const bf16* Bb = B + (size_t)blockIdx.z * sB + (size_t)(blockIdx.x * BN) * K;
    const uint32_t s0 = smem_u32(sm);

    const int lr = tid >> 2, lc = tid & 3;
    uint32_t soA[2], soB[BN / 64];
#pragma unroll
    for (int i = 0; i < 2; i++) soA[i] = tile_off(lr + 64 * i, lc);
#pragma unroll
    for (int i = 0; i < BN / 64; i++) soB[i] = tile_off(lr + 64 * i, lc);

    float acc[MF][8][4];
#pragma unroll
    for (int f = 0; f < MF; f++)
#pragma unroll
        for (int j = 0; j < 8; j++)
#pragma unroll
            for (int e = 0; e < 4; e++) acc[f][j][e] = 0.f;

    const int mid = lane >> 3;
    const int lrow = ((mid & 1) << 3) + (lane & 7);
    const int lchk = mid >> 1;

    // ---- preload tile 0 ----
    {
#pragma unroll
        for (int i = 0; i < 2; i++)
            cp16(s0 + soA[i], Ab + (size_t)(lr + 64 * i) * K + (lc << 3));
#pragma unroll
        for (int i = 0; i < BN / 64; i++)
            cp16(s0 + ATILE + soB[i], Bb + (size_t)(lr + 64 * i) * K + (lc << 3));
        CP_COMMIT();
    }

    const int nt = K >> 5;
    int buf = 0;
    for (int t = 0; t < nt; t++) {
        CP_WAIT0();
        __syncthreads();
        if (t + 1 < nt) {
            uint32_t d = s0 + (buf ^ 1) * (ATILE + BTILE);
            const bf16* An = Ab + (t + 1) * 32;
            const bf16* Bn = Bb + (t + 1) * 32;
#pragma unroll
            for (int i = 0; i < 2; i++)
                cp16(d + soA[i], An + (size_t)(lr + 64 * i) * K + (lc << 3));
#pragma unroll
            for (int i = 0; i < BN / 64; i++)
                cp16(d + ATILE + soB[i], Bn + (size_t)(lr + 64 * i) * K + (lc << 3));
            CP_COMMIT();
        }
        const uint32_t aB = s0 + buf * (ATILE + BTILE);
        const uint32_t bB = aB + ATILE;
#pragma unroll
        for (int s = 0; s < 2; s++) {                    // two k16 steps
            uint32_t a[MF][4], b[8][2];
#pragma unroll
            for (int f = 0; f < MF; f++)
                ldsm4(a[f], aB + tile_off(wm * WM + f * 16 + lrow, s * 2 + lchk));
#pragma unroll
            for (int gq = 0; gq < 4; gq++) {
                uint32_t rr[4];
                ldsm4(rr, bB + tile_off(wn * 64 + gq * 16 + lrow, s * 2 + lchk));
                b[gq * 2][0] = rr[0]; b[gq * 2][1] = rr[2];
                b[gq * 2 + 1][0] = rr[1]; b[gq * 2 + 1][1] = rr[3];
            }
#pragma unroll
            for (int f = 0; f < MF; f++)
#pragma unroll
                for (int j = 0; j < 8; j++) mma16816(acc[f][j], a[f], b[j]);
        }
        __syncthreads();
        buf ^= 1;
    }

    // ---- epilogue ----
    const int g = lane >> 2, t2 = (lane & 3) << 1;
    const int row0 = blockIdx.y * 128 + wm * WM;
    const int col0 = blockIdx.x * BN + wn * WN;
    OT* Cb = C + (size_t)blockIdx.z * sC;
    const float* resb = res ? (res + (size_t)blockIdx.z * sC) : (const float*)0;
#pragma unroll
    for (int f = 0; f < MF; f++) {
#pragma unroll
        for (int j = 0; j < 8; j++) {
            int cc = col0 + j * 8 + t2;
            float bc0 = 0.f, bc1 = 0.f;
            if (bias_mode == 1) { bc0 = bias[cc]; bc1 = bias[cc + 1]; }
#pragma unroll
            for (int h = 0; h < 2; h++) {
                int rr = row0 + f * 16 + g + h * 8;
                float v0 = acc[f][j][h * 2 + 0];
                float v1 = acc[f][j][h * 2 + 1];
                if (bias_mode == 1) { v0 += bc0; v1 += bc1; }
                else if (bias_mode == 2) { float bb = bias[rr]; v0 += bb; v1 += bb; }
                v0 *= alpha; v1 *= alpha;
                size_t o = (size_t)rr * ldC + cc;
                if (resb) { v0 += resb[o]; v1 += resb[o + 1]; }
                if (sizeof(OT) == 4) {
                    *(float2*)((float*)Cb + o) = make_float2(v0, v1);
                } else {
                    __nv_bfloat162 w;
                    w.x = __float2bfloat16(v0); w.y = __float2bfloat16(v1);
                    *(__nv_bfloat162*)((bf16*)Cb + o) = w;
                }
            }
        }
    }
}

// ---------------- GroupNorm stats ----------------
__global__ void gn_stats_kernel(const float* __restrict__ x) {
    int bg = blockIdx.x;
    int b = bg >> 5, g = bg & 31;
    const float* base = x + (size_t)b * HW * CH + g * CPG;
    float s = 0.f, ss = 0.f;
    for (int p = threadIdx.x; p < HW; p += blockDim.x) {
        const float4* r = (const float4*)(base + (size_t)p * CH);
#pragma unroll
        for (int i = 0; i < 4; i++) {
            float4 v = r[i];
            s  += v.x + v.y + v.z + v.w;
            ss += v.x * v.x + v.y * v.y + v.z * v.z + v.w * v.w;
        }
    }
    __shared__ float sh[256], sh2[256];
    int t = threadIdx.x;
    sh[t] = s; sh2[t] = ss;
    __syncthreads();
    for (int o = 128; o > 0; o >>= 1) {
        if (t < o) { sh[t] += sh[t + o]; sh2[t] += sh2[t + o]; }
        __syncthreads();
    }
    if (t == 0) {
        float inv = 1.f / (float)(HW * CPG);
        float mean = sh[0] * inv;
        float var = sh2[0] * inv - mean * mean;
        g_stats[bg * 2]     = mean;
        g_stats[bg * 2 + 1] = rsqrtf(var + EPSV);
    }
}

// ---------------- GroupNorm apply -> bf16 ----------------
__global__ void gn_apply_kernel(const float* __restrict__ x,
                                const float* __restrict__ gamma,
                                const float* __restrict__ beta) {
    size_t i = ((size_t)blockIdx.x * blockDim.x + threadIdx.x) * 4;
    int c = (int)(i % CH);
    int b = (int)(i / ((size_t)HW * CH));
    int bg = b * NGROUP + (c >> 4);
    float mean = g_stats[bg * 2], rstd = g_stats[bg * 2 + 1];
    float4 v  = *(const float4*)(x + i);
    float4 ga = *(const float4*)(gamma + c);
    float4 be = *(const float4*)(beta + c);
    __nv_bfloat162 o01, o23;
    o01.x = __float2bfloat16((v.x - mean) * rstd * ga.x + be.x);
    o01.y = __float2bfloat16((v.y - mean) * rstd * ga.y + be.y);
    o23.x = __float2bfloat16((v.z - mean) * rstd * ga.z + be.z);
    o23.y = __float2bfloat16((v.w - mean) * rstd * ga.w + be.w);
    *(__nv_bfloat162*)(g_xb + i)     = o01;
    *(__nv_bfloat162*)(g_xb + i + 2) = o23;
}

// ---------------- weight transpose fp32 [K,N] -> bf16 [N,K] ----------------
__global__ void transpose_w_kernel(const float* __restrict__ w, bf16* __restrict__ wT) {
    __shared__ float t[32][33];
    int c0 = blockIdx.x * 32, d0 = blockIdx.y * 32;
    int tx = threadIdx.x, ty = threadIdx.y;
#pragma unroll
    for (int r = 0; r < 4; r++) {
        int row = ty + r * 8;
        t[row][tx] = w[(size_t)(c0 + row) * CH + d0 + tx];
    }
    __syncthreads();
#pragma unroll
    for (int r = 0; r < 4; r++) {
        int row = ty + r * 8;
        wT[(size_t)(d0 + row) * CH + c0 + tx] = __float2bfloat16(t[tx][row]);
    }
}

// ---------------- row softmax (fp32 in -> bf16 out) ----------------
__global__ void softmax_kernel(const float* __restrict__ S, bf16* __restrict__ P) {
    size_t row = blockIdx.x;
    const float* p = S + row * HW;
    bf16* q = P + row * HW;
    int t = threadIdx.x;
    float v[16];
    float m = -1e30f;
#pragma unroll
    for (int i = 0; i < 16; i++) { v[i] = p[i * 256 + t]; m = fmaxf(m, v[i]); }
    __shared__ float sh[256];
    sh[t] = m; __syncthreads();
    for (int o = 128; o > 0; o >>= 1) { if (t < o) sh[t] = fmaxf(sh[t], sh[t + o]); __syncthreads(); }
    m = sh[0];
    __syncthreads();
    float s = 0.f;
#pragma unroll
    for (int i = 0; i < 16; i++) { v[i] = __expf(v[i] - m); s += v[i]; }
    sh[t] = s; __syncthreads();
    for (int o = 128; o > 0; o >>= 1) { if (t < o) sh[t] += sh[t + o]; __syncthreads(); }
    float inv = 1.f / sh[0];
#pragma unroll
    for (int i = 0; i < 16; i++) q[i * 256 + t] = __float2bfloat16(v[i] * inv);
}

extern "C" void kernel_launch(void* const* d_in, const int* in_sizes, int n_in,
                              void* d_out, int out_size) {
    const float* x     = (const float*)d_in[0];
    const float* gamma = (const float*)d_in[1];
    const float* beta  = (const float*)d_in[2];
    const float* wq    = (const float*)d_in[3];
    const float* bq    = (const float*)d_in[4];
    const float* wk    = (const float*)d_in[5];
    const float* bk    = (const float*)d_in[6];
    const float* wv    = (const float*)d_in[7];
    const float* bv    = (const float*)d_in[8];
    const float* wo    = (const float*)d_in[9];
    const float* bo    = (const float*)d_in[10];
    float* out = (float*)d_out;

    bf16 *pxb, *pqb, *pkb, *pvt, *paob, *ppb;
    bf16 *pwqT, *pwkT, *pwvT, *pwoT;
    float *ps;
    cudaGetSymbolAddress((void**)&pxb,  g_xb);
    cudaGetSymbolAddress((void**)&pqb,  g_qb);
    cudaGetSymbolAddress((void**)&pkb,  g_kb);
    cudaGetSymbolAddress((void**)&pvt,  g_vt);
    cudaGetSymbolAddress((void**)&paob, g_aob);
    cudaGetSymbolAddress((void**)&ppb,  g_pb);
    cudaGetSymbolAddress((void**)&ps,   g_s);
    cudaGetSymbolAddress((void**)&pwqT, g_wqT);
    cudaGetSymbolAddress((void**)&pwkT, g_wkT);
    cudaGetSymbolAddress((void**)&pwvT, g_wvT);
    cudaGetSymbolAddress((void**)&pwoT, g_woT);

    // GroupNorm
    gn_stats_kernel<<<BATCH * NGROUP, 256>>>(x);
    gn_apply_kernel<<<(BATCH * HW * CH / 4) / 256, 256>>>(x, gamma, beta);

    // weight transposes (K-major bf16)
    dim3 bt(32, 8);
    dim3 gw(16, 16);
    transpose_w_kernel<<<gw, bt>>>(wq, pwqT);
    transpose_w_kernel<<<gw, bt>>>(wk, pwkT);
    transpose_w_kernel<<<gw, bt>>>(wv, pwvT);
    transpose_w_kernel<<<gw, bt>>>(wo, pwoT);

    const float scale = 0.0441941738241592f;  // 1/sqrt(512)

    // Q/K projections: [16384 x 512] x [512 x 512]
    dim3 gproj(CH / 256, (BATCH * HW) / 128, 1);  // (2, 128)
    wmma_gemm<bf16, 256, 2><<<gproj, 256>>>(pxb, pwqT, pqb, CH, CH, 0, 0, 0,
                                            bq, 1, 0, scale);
    wmma_gemm<bf16, 256, 2><<<gproj, 256>>>(pxb, pwkT, pkb, CH, CH, 0, 0, 0,
                                            bk, 1, 0, 1.f);

    // V^T directly: vt[c][n] = sum_k wvT[c,k] * xb[n,k]  (bias per row c)
    dim3 gvt(HW / 256, CH / 128, BATCH);          // (16, 4, 4)
    wmma_gemm<bf16, 256, 2><<<gvt, 256>>>(pwvT, pxb, pvt, CH, HW,
                                          0, (long long)HW * CH, (long long)CH * HW,
                                          bv, 2, 0, 1.f);

    // scores: per batch [4096 x 512] x [4096 x 512]^T -> fp32
    dim3 gsc(HW / 256, HW / 128, BATCH);          // (16, 32, 4)
    wmma_gemm<float, 256, 2><<<gsc, 256>>>(pqb, pkb, ps, CH, HW,
                                           (long long)HW * CH, (long long)HW * CH,
                                           (long long)HW * HW, 0, 0, 0, 1.f);

    softmax_kernel<<<BATCH * HW, 256>>>(ps, ppb);

    // AV: per batch [4096 x 4096] x [512 x 4096]^T -> bf16
    dim3 gav(CH / 256, HW / 128, BATCH);          // (2, 32, 4)
    wmma_gemm<bf16, 256, 2><<<gav, 256>>>(ppb, pvt, paob, HW, CH,
                                          (long long)HW * HW, (long long)CH * HW,
                                          (long long)HW * CH, 0, 0, 0, 1.f);

    // out projection + residual -> fp32 out
    wmma_gemm<float, 256, 2><<<gproj, 256>>>(paob, pwoT, out, CH, CH, 0, 0, 0,
                                             bo, 1, x, 1.f);
}